// round 2
// baseline (speedup 1.0000x reference)
#include <cuda_runtime.h>
#include <cuda_bf16.h>

// Problem constants (fixed by the dataset)
#define NN    10000          // nodes
#define EE    320000         // edges (before self loops)
#define BB    64             // graphs
#define IN_C  128            // in channels
#define EC    64             // edge channels
#define HID   256            // hidden
#define MLPD  512
#define NCO   4
#define K1    (2*IN_C + EC)  // 320
#define K23   (2*HID + EC)   // 576
#define EPSV  1e-5f
#define MAXSZ 40.0f

// ---------------- scratch (static device globals; no allocation) ----------------
__device__ int   g_deg[NN];
__device__ int   g_off[NN + 1];
__device__ int   g_cur[NN];
__device__ int   g_src[EE];
__device__ int   g_eid[EE];
__device__ __align__(16) float g_Sea[NN * EC];
__device__ __align__(16) float g_A[NN * K23];     // concat buffer  (23 MB)
__device__ __align__(16) float g_h[NN * HID];     // layer activation
__device__ __align__(16) float g_hp[NN * HID];    // pre-BN (post-relu) activation
__device__ float g_stats[2 * HID];  // col sum / sumsq
__device__ float g_pool[BB * HID];
__device__ float g_cnt[BB];

// ---------------- tiny utility kernels ----------------
__global__ void zero_deg_kernel() {
    int i = blockIdx.x * blockDim.x + threadIdx.x;
    if (i < NN) g_deg[i] = 0;
}
__global__ void zero_stats_kernel() {
    int i = threadIdx.x;
    if (i < 2 * HID) g_stats[i] = 0.f;
}
__global__ void zero_pool_kernel() {
    int i = blockIdx.x * blockDim.x + threadIdx.x;
    if (i < BB * HID) g_pool[i] = 0.f;
    if (i < BB) g_cnt[i] = 0.f;
}

// ---------------- CSR build ----------------
__global__ void hist_kernel(const int* __restrict__ ei) {
    int e = blockIdx.x * blockDim.x + threadIdx.x;
    if (e < EE) {
        int d = ei[EE + e];  // dst row
        atomicAdd(&g_deg[d], 1);
    }
}

// single block, 1024 threads, exclusive scan of g_deg -> g_off / g_cur
__global__ void scan_kernel() {
    const int CH = 10;  // 10000 / 1024 -> 10 per thread
    int tid = threadIdx.x;
    int base = tid * CH;
    int local[CH];
    int s = 0;
#pragma unroll
    for (int i = 0; i < CH; i++) {
        int idx = base + i;
        int v = (idx < NN) ? g_deg[idx] : 0;
        local[i] = s;
        s += v;
    }
    __shared__ int sh[1024];
    sh[tid] = s;
    __syncthreads();
    for (int d = 1; d < 1024; d <<= 1) {
        int t = (tid >= d) ? sh[tid - d] : 0;
        __syncthreads();
        sh[tid] += t;
        __syncthreads();
    }
    int excl = sh[tid] - s;
#pragma unroll
    for (int i = 0; i < CH; i++) {
        int idx = base + i;
        if (idx < NN) {
            int o = excl + local[i];
            g_off[idx] = o;
            g_cur[idx] = o;
        }
    }
    if (tid == 0) g_off[NN] = EE;
}

__global__ void fill_kernel(const int* __restrict__ ei) {
    int e = blockIdx.x * blockDim.x + threadIdx.x;
    if (e < EE) {
        int s = ei[e];
        int d = ei[EE + e];
        int pos = atomicAdd(&g_cur[d], 1);
        g_src[pos] = s;
        g_eid[pos] = e;
    }
}

// ---------------- S_ea aggregation (once per call; self loop contributes 1.0) ----------------
__global__ void sea_kernel(const float* __restrict__ ea) {
    int v = blockIdx.x;
    int t = threadIdx.x;  // 64
    int s0 = g_off[v], s1 = g_off[v + 1];
    float acc = 1.0f;  // self-loop edge attr = 1.0
    for (int j = s0; j < s1; j++) {
        int eid = g_eid[j];
        acc += ea[eid * EC + t];
    }
    g_Sea[v * EC + t] = acc;
}

// ---------------- per-layer aggregation + concat materialization ----------------
// A row v = [deg(v)*h[v] (D), h[v]+sum_src h[src] (D), Sea (EC)]
// USE_G: read layer input from the device-global g_h (NEVER pass g_h as a
// host-side kernel argument — the host shadow symbol is not a device address).
template <int D, int K, bool USE_G>
__global__ void agg_kernel(const float* __restrict__ xin) {
    const float* __restrict__ hin = USE_G ? (const float*)g_h : xin;
    int v = blockIdx.x;
    int t = threadIdx.x;  // D threads
    int s0 = g_off[v], s1 = g_off[v + 1];
    float self = hin[v * D + t];
    float acc = self;  // self loop
    int j = s0;
    for (; j + 4 <= s1; j += 4) {
        int a = g_src[j], b = g_src[j + 1], c = g_src[j + 2], d = g_src[j + 3];
        acc += hin[a * D + t] + hin[b * D + t] + hin[c * D + t] + hin[d * D + t];
    }
    for (; j < s1; j++) acc += hin[g_src[j] * D + t];

    float degf = (float)(s1 - s0 + 1);
    float* Arow = &g_A[(size_t)v * K];
    Arow[t]     = degf * self;
    Arow[D + t] = acc;
    if (t < EC) Arow[2 * D + t] = g_Sea[v * EC + t];
}

// ---------------- fp32 SGEMM: out = relu(A[N,K] @ W[K,256] + deg*b) ----------------
// BM=128 BN=64 BK=16, 256 threads, 8x4 micro-tile
template <int K>
__global__ __launch_bounds__(256) void gemm_kernel(const float* __restrict__ W,
                                                   const float* __restrict__ bias) {
    const int BM = 128, BN = 64, BK = 16;
    __shared__ float As[BK][BM];
    __shared__ float Bs[BK][BN];

    int tid = threadIdx.x;
    int tr = tid / 16;  // 0..15
    int tc = tid % 16;  // 0..15
    int rowBase = blockIdx.y * BM;
    int colBase = blockIdx.x * BN;

    float acc[8][4];
#pragma unroll
    for (int i = 0; i < 8; i++)
#pragma unroll
        for (int jx = 0; jx < 4; jx++) acc[i][jx] = 0.f;

    int aRow = tid / 4;        // 0..63
    int aK4  = (tid % 4) * 4;  // k offset within tile
    int bRow = tid / 16;       // 0..15
    int bC4  = (tid % 16) * 4;

    for (int k0 = 0; k0 < K; k0 += BK) {
        // load A tile (2 float4 per thread), transposed into As[k][m]
#pragma unroll
        for (int half = 0; half < 2; half++) {
            int r = aRow + half * 64;
            int grow = rowBase + r;
            float4 va = make_float4(0.f, 0.f, 0.f, 0.f);
            if (grow < NN)
                va = *(const float4*)&g_A[(size_t)grow * K + k0 + aK4];
            As[aK4 + 0][r] = va.x;
            As[aK4 + 1][r] = va.y;
            As[aK4 + 2][r] = va.z;
            As[aK4 + 3][r] = va.w;
        }
        // load B tile (1 float4 per thread)
        float4 vb = *(const float4*)&W[(size_t)(k0 + bRow) * HID + colBase + bC4];
        *(float4*)&Bs[bRow][bC4] = vb;
        __syncthreads();

#pragma unroll
        for (int k = 0; k < BK; k++) {
            float a[8], b[4];
#pragma unroll
            for (int i = 0; i < 8; i++) a[i] = As[k][tr * 8 + i];
#pragma unroll
            for (int jx = 0; jx < 4; jx++) b[jx] = Bs[k][tc * 4 + jx];
#pragma unroll
            for (int i = 0; i < 8; i++)
#pragma unroll
                for (int jx = 0; jx < 4; jx++) acc[i][jx] += a[i] * b[jx];
        }
        __syncthreads();
    }

    // epilogue: + deg*bias, relu, store
#pragma unroll
    for (int i = 0; i < 8; i++) {
        int row = rowBase + tr * 8 + i;
        if (row < NN) {
            float dg = (float)(g_off[row + 1] - g_off[row] + 1);
            int col = colBase + tc * 4;
            float4 o;
            o.x = fmaxf(acc[i][0] + dg * bias[col + 0], 0.f);
            o.y = fmaxf(acc[i][1] + dg * bias[col + 1], 0.f);
            o.z = fmaxf(acc[i][2] + dg * bias[col + 2], 0.f);
            o.w = fmaxf(acc[i][3] + dg * bias[col + 3], 0.f);
            *(float4*)&g_hp[(size_t)row * HID + col] = o;
        }
    }
}

// ---------------- column stats (sum, sumsq) over g_hp ----------------
__global__ void stats_kernel() {
    const int ROWS = 250;  // 40 blocks * 250 = 10000
    int c = threadIdx.x;   // 256
    int r0 = blockIdx.x * ROWS;
    float s = 0.f, s2 = 0.f;
    for (int r = r0; r < r0 + ROWS; r++) {
        float v = g_hp[(size_t)r * HID + c];
        s += v;
        s2 += v * v;
    }
    atomicAdd(&g_stats[c], s);
    atomicAdd(&g_stats[HID + c], s2);
}

// ---------------- BN apply + relu -> g_h ----------------
__global__ void bn_kernel(const float* __restrict__ gamma, const float* __restrict__ beta) {
    int idx = blockIdx.x * blockDim.x + threadIdx.x;  // over N*HID/4
    if (idx >= NN * HID / 4) return;
    int f = idx * 4;
    int c = f & (HID - 1);
    float4 v = *(const float4*)&g_hp[f];
    float invN = 1.0f / (float)NN;
    float4 o;
    {
        float mu = g_stats[c] * invN;
        float var = g_stats[HID + c] * invN - mu * mu;
        float rs = rsqrtf(var + EPSV);
        o.x = fmaxf((v.x - mu) * rs * gamma[c] + beta[c], 0.f);
    }
    {
        float mu = g_stats[c + 1] * invN;
        float var = g_stats[HID + c + 1] * invN - mu * mu;
        float rs = rsqrtf(var + EPSV);
        o.y = fmaxf((v.y - mu) * rs * gamma[c + 1] + beta[c + 1], 0.f);
    }
    {
        float mu = g_stats[c + 2] * invN;
        float var = g_stats[HID + c + 2] * invN - mu * mu;
        float rs = rsqrtf(var + EPSV);
        o.z = fmaxf((v.z - mu) * rs * gamma[c + 2] + beta[c + 2], 0.f);
    }
    {
        float mu = g_stats[c + 3] * invN;
        float var = g_stats[HID + c + 3] * invN - mu * mu;
        float rs = rsqrtf(var + EPSV);
        o.w = fmaxf((v.w - mu) * rs * gamma[c + 3] + beta[c + 3], 0.f);
    }
    *(float4*)&g_h[f] = o;
}

// ---------------- pooling ----------------
__global__ void pool_kernel(const int* __restrict__ batch) {
    int idx = blockIdx.x * blockDim.x + threadIdx.x;  // N*HID
    if (idx >= NN * HID) return;
    int v = idx / HID;
    int c = idx & (HID - 1);
    int b = batch[v];
    atomicAdd(&g_pool[b * HID + c], g_h[idx]);
    if (c == 0) atomicAdd(&g_cnt[b], 1.0f);
}

// ---------------- final MLP (one block per graph) ----------------
__global__ __launch_bounds__(512) void mlp_kernel(const float* __restrict__ neighbor,
                                                  const float* __restrict__ fc1w,
                                                  const float* __restrict__ fc1b,
                                                  const float* __restrict__ fc2w,
                                                  const float* __restrict__ fc2b,
                                                  float* __restrict__ out) {
    const int ZD = HID + 1 + IN_C;  // 385
    __shared__ float z[ZD];
    __shared__ float hbuf[MLPD];
    int b = blockIdx.x;
    int t = threadIdx.x;
    if (t < HID) z[t] = g_pool[b * HID + t];
    else if (t == HID) z[t] = g_cnt[b] / MAXSZ;
    else if (t < ZD) z[t] = neighbor[b * IN_C + (t - HID - 1)];
    __syncthreads();

    float acc = fc1b[t];
    for (int k = 0; k < ZD; k++) acc += z[k] * fc1w[k * MLPD + t];
    hbuf[t] = fmaxf(acc, 0.f);
    __syncthreads();

    if (t < NCO) {
        float o = fc2b[t];
        for (int k = 0; k < MLPD; k++) o += hbuf[k] * fc2w[k * NCO + t];
        out[b * NCO + t] = o;
    }
}

// ---------------- launch ----------------
extern "C" void kernel_launch(void* const* d_in, const int* in_sizes, int n_in,
                              void* d_out, int out_size) {
    const float* x        = (const float*)d_in[0];
    const int*   ei       = (const int*)d_in[1];
    const float* ea       = (const float*)d_in[2];
    const int*   batch    = (const int*)d_in[3];
    const float* neighbor = (const float*)d_in[4];
    const float* W1  = (const float*)d_in[5];
    const float* b1  = (const float*)d_in[6];
    const float* g1  = (const float*)d_in[7];
    const float* be1 = (const float*)d_in[8];
    const float* W2  = (const float*)d_in[9];
    const float* b2  = (const float*)d_in[10];
    const float* g2  = (const float*)d_in[11];
    const float* be2 = (const float*)d_in[12];
    const float* W3  = (const float*)d_in[13];
    const float* b3  = (const float*)d_in[14];
    const float* g3  = (const float*)d_in[15];
    const float* be3 = (const float*)d_in[16];
    const float* fc1w = (const float*)d_in[17];
    const float* fc1b = (const float*)d_in[18];
    const float* fc2w = (const float*)d_in[19];
    const float* fc2b = (const float*)d_in[20];
    float* out = (float*)d_out;

    // CSR build
    zero_deg_kernel<<<(NN + 255) / 256, 256>>>();
    hist_kernel<<<(EE + 255) / 256, 256>>>(ei);
    scan_kernel<<<1, 1024>>>();
    fill_kernel<<<(EE + 255) / 256, 256>>>(ei);
    sea_kernel<<<NN, EC>>>(ea);

    dim3 ggrid(HID / 64, (NN + 127) / 128);

    // layer 1 (input = x, passed as argument)
    agg_kernel<IN_C, K1, false><<<NN, IN_C>>>(x);
    zero_stats_kernel<<<1, 512>>>();
    gemm_kernel<K1><<<ggrid, 256>>>(W1, b1);
    stats_kernel<<<40, 256>>>();
    bn_kernel<<<(NN * HID / 4 + 255) / 256, 256>>>(g1, be1);

    // layer 2 (input = g_h, accessed from device code)
    agg_kernel<HID, K23, true><<<NN, HID>>>(nullptr);
    zero_stats_kernel<<<1, 512>>>();
    gemm_kernel<K23><<<ggrid, 256>>>(W2, b2);
    stats_kernel<<<40, 256>>>();
    bn_kernel<<<(NN * HID / 4 + 255) / 256, 256>>>(g2, be2);

    // layer 3
    agg_kernel<HID, K23, true><<<NN, HID>>>(nullptr);
    zero_stats_kernel<<<1, 512>>>();
    gemm_kernel<K23><<<ggrid, 256>>>(W3, b3);
    stats_kernel<<<40, 256>>>();
    bn_kernel<<<(NN * HID / 4 + 255) / 256, 256>>>(g3, be3);

    // pooling + MLP
    zero_pool_kernel<<<(BB * HID + 255) / 256, 256>>>();
    pool_kernel<<<(NN * HID + 255) / 256, 256>>>(batch);
    mlp_kernel<<<BB, MLPD>>>(neighbor, fc1w, fc1b, fc2w, fc2b, out);
}